// round 14
// baseline (speedup 1.0000x reference)
#include <cuda_runtime.h>
#include <cuda_bf16.h>
#include <math.h>
#include <stdint.h>

// ---------------------------------------------------------------------------
// Problem constants
// ---------------------------------------------------------------------------
#define T_TOK   1024
#define HID     2880
#define NH      64
#define KVH     8
#define HD      64
#define INTER   2880
#define QKV_DIM (HD*(NH+2*KVH))      // 5120
#define O_DIM   (NH*HD)              // 4096
#define U_DIM   (2*INTER)            // 5760
#define SM_SCALE 0.125f
#define EPSF    1e-5f

#define NPAD_OUT 3072
#define NPAD_UP  5888
#define NPAD_DN  3072

// ---------------------------------------------------------------------------
// Scratch
// ---------------------------------------------------------------------------
__device__ float g_qkv[T_TOK * QKV_DIM];
__device__ float g_h  [T_TOK * HID];
__device__ float g_t  [T_TOK * HID];
__device__ float g_o  [T_TOK * O_DIM];
__device__ float g_act[T_TOK * INTER];
__device__ float g_ws [6 * T_TOK * QKV_DIM];
__device__ float g_rope[T_TOK * 64];

// ---------------------------------------------------------------------------
// PTX helpers
// ---------------------------------------------------------------------------
__device__ __forceinline__ uint32_t smem_u32(const void* p) {
    uint32_t a;
    asm("{ .reg .u64 t; cvta.to.shared.u64 t, %1; cvt.u32.u64 %0, t; }" : "=r"(a) : "l"(p));
    return a;
}
__device__ __forceinline__ void cp16(uint32_t dst, const void* src) {
    asm volatile("cp.async.cg.shared.global [%0], [%1], 16;" :: "r"(dst), "l"(src));
}
__device__ __forceinline__ void cp_commit() {
    asm volatile("cp.async.commit_group;" ::: "memory");
}
__device__ __forceinline__ void cp_wait1() {
    asm volatile("cp.async.wait_group 1;" ::: "memory");
}
__device__ __forceinline__ void cp_wait0() {
    asm volatile("cp.async.wait_group 0;" ::: "memory");
}
__device__ __forceinline__ void mma_tf32(float* c, const uint32_t* a, const uint32_t* b) {
    asm volatile("mma.sync.aligned.m16n8k8.row.col.f32.tf32.tf32.f32 "
        "{%0,%1,%2,%3}, {%4,%5,%6,%7}, {%8,%9}, {%0,%1,%2,%3};"
        : "+f"(c[0]), "+f"(c[1]), "+f"(c[2]), "+f"(c[3])
        : "r"(a[0]), "r"(a[1]), "r"(a[2]), "r"(a[3]), "r"(b[0]), "r"(b[1]));
}
__device__ __forceinline__ float tf32r(float x) {
    uint32_t o;
    asm("cvt.rna.tf32.f32 %0, %1;" : "=r"(o) : "f"(x));
    return __uint_as_float(o);
}
__device__ __forceinline__ uint32_t tf32u(float x) {
    uint32_t o;
    asm("cvt.rna.tf32.f32 %0, %1;" : "=r"(o) : "f"(x));
    return o;
}

// FMA-pipe exp
__device__ __forceinline__ float fast_exp(float x) {
    x = fmaxf(x, -80.f);
    const float y = x * 1.4426950408889634f;
    const float fn = y + 12582912.f;
    const int ni = __float_as_int(fn) - 0x4B400000;
    const float f = y - (fn - 12582912.f);
    float p = 1.3333558146e-3f;
    p = fmaf(p, f, 9.6181291076e-3f);
    p = fmaf(p, f, 5.5504108664e-2f);
    p = fmaf(p, f, 2.4022650696e-1f);
    p = fmaf(p, f, 6.9314718056e-1f);
    p = fmaf(p, f, 1.0f);
    return p * __int_as_float((ni + 127) << 23);
}

// ---------------------------------------------------------------------------
// tf32 single-pass GEMM, split-K S slices (unchanged, proven)
// ---------------------------------------------------------------------------
#define NF32 36
#define A_F  4608
#define B_F  9216
#define GSMEM_TOTAL ((2 * A_F + 2 * B_F) * 4)

__device__ __forceinline__ void fill_tiles_tf32(
    uint32_t aT, uint32_t bT,
    const float* __restrict__ A, const float* __restrict__ W,
    int K, int m0, int n0, int k0, int Nrows, int tid)
{
    #pragma unroll
    for (int i = 0; i < 4; i++) {
        int q = tid + 256 * i;
        int r = q >> 3, c = q & 7;
        cp16(aT + r * 144 + c * 16, A + (size_t)(m0 + r) * K + k0 + c * 4);
    }
    #pragma unroll
    for (int i = 0; i < 8; i++) {
        int q = tid + 256 * i;
        int r = q >> 3, c = q & 7;
        int rw = n0 + r; if (rw >= Nrows) rw = Nrows - 1;
        cp16(bT + r * 144 + c * 16, W + (size_t)rw * K + k0 + c * 4);
    }
}

__global__ __launch_bounds__(256) void tf32_gemm_sk(
    const float* __restrict__ A, const float* __restrict__ W,
    float* __restrict__ ws, int K, int Npad, int Nrows, int S)
{
    extern __shared__ char smem[];
    const uint32_t sbase = smem_u32(smem);
    const uint32_t tA[2] = { sbase,               sbase + A_F * 4 };
    const uint32_t tB[2] = { sbase + 2 * A_F * 4, sbase + 2 * A_F * 4 + B_F * 4 };
    float* smf = (float*)smem;

    const int tid  = threadIdx.x;
    const int wid  = tid >> 5;
    const int lane = tid & 31;
    const int wm   = wid >> 2;
    const int wn   = wid & 3;
    const int g    = lane >> 2;
    const int qd   = lane & 3;
    const int m0 = blockIdx.x * 128;
    const int n0 = blockIdx.y * 256;
    const int z  = blockIdx.z;
    const int NC = K >> 5;
    const int cb = (z * NC) / S;
    const int ce = ((z + 1) * NC) / S;

    float acc[4][8][4];
    #pragma unroll
    for (int i = 0; i < 4; i++)
        #pragma unroll
        for (int j = 0; j < 8; j++)
            #pragma unroll
            for (int q = 0; q < 4; q++) acc[i][j][q] = 0.f;

    fill_tiles_tf32(tA[0], tB[0], A, W, K, m0, n0, cb << 5, Nrows, tid);
    cp_commit();

    for (int c = cb; c < ce; c++) {
        const int b = (c - cb) & 1;
        if (c + 1 < ce) {
            const int nb = (c + 1 - cb) & 1;
            fill_tiles_tf32(tA[nb], tB[nb], A, W, K, m0, n0,
                            (c + 1) << 5, Nrows, tid);
            cp_commit();
            cp_wait1();
        } else {
            cp_wait0();
        }
        __syncthreads();

        const float* As = smf + b * A_F;
        const float* Bs = smf + 2 * A_F + b * B_F;

        #pragma unroll
        for (int ks = 0; ks < 4; ks++) {
            const int k0 = ks * 8;
            uint32_t a[4][4], bb[8][2];
            #pragma unroll
            for (int mf = 0; mf < 4; mf++) {
                const int row = wm * 64 + mf * 16 + g;
                a[mf][0] = tf32u(As[row * NF32 + k0 + qd]);
                a[mf][1] = tf32u(As[(row + 8) * NF32 + k0 + qd]);
                a[mf][2] = tf32u(As[row * NF32 + k0 + 4 + qd]);
                a[mf][3] = tf32u(As[(row + 8) * NF32 + k0 + 4 + qd]);
            }
            #pragma unroll
            for (int nf = 0; nf < 8; nf++) {
                const int rowb = wn * 64 + nf * 8 + g;
                bb[nf][0] = tf32u(Bs[rowb * NF32 + k0 + qd]);
                bb[nf][1] = tf32u(Bs[rowb * NF32 + k0 + 4 + qd]);
            }
            #pragma unroll
            for (int mf = 0; mf < 4; mf++)
                #pragma unroll
                for (int nf = 0; nf < 8; nf++)
                    mma_tf32(acc[mf][nf], a[mf], bb[nf]);
        }
        __syncthreads();
    }

    float* wz = ws + (size_t)z * T_TOK * Npad;
    const int t = lane & 3;
    #pragma unroll
    for (int nf = 0; nf < 8; nf++) {
        const int col = n0 + wn * 64 + nf * 8 + t * 2;
        #pragma unroll
        for (int mf = 0; mf < 4; mf++) {
            const int r0 = m0 + wm * 64 + mf * 16 + g;
            *(float2*)(wz + (size_t)r0 * Npad + col) =
                make_float2(acc[mf][nf][0], acc[mf][nf][1]);
            *(float2*)(wz + (size_t)(r0 + 8) * Npad + col) =
                make_float2(acc[mf][nf][2], acc[mf][nf][3]);
        }
    }
}

// ---------------------------------------------------------------------------
// Rope table
// ---------------------------------------------------------------------------
__global__ void rope_table_kernel(float* __restrict__ tab)
{
    const int t = blockIdx.x;
    const int i = threadIdx.x;
    const float PI = 3.14159265358979323846f;
    const float rope_base = 150000.f;
    const float freq = powf(rope_base, (float)i / 32.f);
    const float conc = 0.1f * logf(32.f) + 1.f;
    const float lg = logf(rope_base);
    const float low  = 32.f * logf(4096.f / (32.f * 2.f * PI)) / lg;
    const float high = 32.f * logf(4096.f / (2.f * PI)) / lg;
    const float interp = 1.f / (32.f * freq);
    const float extrap = 1.f / freq;
    float ramp = ((float)i - low) / (high - low);
    ramp = fminf(fmaxf(ramp, 0.f), 1.f);
    const float mask = 1.f - ramp;
    const float invf = interp * (1.f - mask) + extrap * mask;
    const float ang = (float)t * invf;
    tab[t * 64 + i]      = cosf(ang) * conc;
    tab[t * 64 + 32 + i] = sinf(ang) * conc;
}

// ---------------------------------------------------------------------------
// RMSNorm (plain fp32 output)
// ---------------------------------------------------------------------------
__global__ __launch_bounds__(256) void rmsnorm_kernel(
    const float* __restrict__ x, const float* __restrict__ scale,
    float* __restrict__ out)
{
    const int row = blockIdx.x;
    const float* xr = x + (size_t)row * HID;
    float s = 0.f;
    for (int i = threadIdx.x; i < HID; i += 256) { float v = xr[i]; s += v * v; }
    __shared__ float red[256];
    red[threadIdx.x] = s;
    __syncthreads();
    for (int off = 128; off > 0; off >>= 1) {
        if (threadIdx.x < off) red[threadIdx.x] += red[threadIdx.x + off];
        __syncthreads();
    }
    const float inv = rsqrtf(red[0] / (float)HID + EPSF);
    float* orow = out + (size_t)row * HID;
    for (int i = threadIdx.x; i < HID; i += 256)
        orow[i] = xr[i] * inv * scale[i];
}

// ---------------------------------------------------------------------------
// QKV reduce (6 slices) + bias + RoPE -> qkv
// ---------------------------------------------------------------------------
__global__ __launch_bounds__(256) void reduce_qkv_rope_kernel(
    const float* __restrict__ ws, const float* __restrict__ bias,
    const float* __restrict__ tab, float* __restrict__ qkv)
{
    const int t = blockIdx.x;
    const int tid = threadIdx.x;
    const size_t SL = (size_t)T_TOK * QKV_DIM;
    const float* base = ws + (size_t)t * QKV_DIM;
    float* outr = qkv + (size_t)t * QKV_DIM;
    const float* tr = tab + t * 64;

    for (int p = tid; p < 72 * 32; p += 256) {
        const int head = p >> 5, d = p & 31;
        const int c1 = head * 64 + d, c2 = c1 + 32;
        float s1 = bias[c1], s2 = bias[c2];
        #pragma unroll
        for (int z = 0; z < 6; z++) {
            s1 += base[z * SL + c1];
            s2 += base[z * SL + c2];
        }
        const float cc = tr[d], ss = tr[32 + d];
        outr[c1] = s1 * cc - s2 * ss;
        outr[c2] = s2 * cc + s1 * ss;
    }
    for (int c = 4608 + tid; c < QKV_DIM; c += 256) {
        float s = bias[c];
        #pragma unroll
        for (int z = 0; z < 6; z++) s += base[z * SL + c];
        outr[c] = s;
    }
}

// ---------------------------------------------------------------------------
// out reduce (3) + bias + residual -> h, then rmsnorm -> fp32 g_t
// ---------------------------------------------------------------------------
__global__ __launch_bounds__(256) void reduce_out_rms_kernel(
    const float* __restrict__ ws, const float* __restrict__ bias,
    const float* __restrict__ res, const float* __restrict__ scale,
    float* __restrict__ h, float* __restrict__ tn)
{
    __shared__ float row[HID];
    __shared__ float red[256];
    const int t = blockIdx.x;
    const int tid = threadIdx.x;
    const size_t SL = (size_t)T_TOK * NPAD_OUT;
    const float* base = ws + (size_t)t * NPAD_OUT;
    const float* xr = res + (size_t)t * HID;
    float* hr = h + (size_t)t * HID;

    float sq = 0.f;
    for (int c = tid * 4; c < HID; c += 1024) {
        const float4 a = *(const float4*)(base + c);
        const float4 b = *(const float4*)(base + SL + c);
        const float4 d = *(const float4*)(base + 2 * SL + c);
        const float4 bb = *(const float4*)(bias + c);
        const float4 rv = *(const float4*)(xr + c);
        float4 v;
        v.x = a.x + b.x + d.x + bb.x + rv.x;
        v.y = a.y + b.y + d.y + bb.y + rv.y;
        v.z = a.z + b.z + d.z + bb.z + rv.z;
        v.w = a.w + b.w + d.w + bb.w + rv.w;
        *(float4*)(row + c) = v;
        *(float4*)(hr + c) = v;
        sq += v.x * v.x + v.y * v.y + v.z * v.z + v.w * v.w;
    }
    red[tid] = sq;
    __syncthreads();
    for (int off = 128; off > 0; off >>= 1) {
        if (tid < off) red[tid] += red[tid + off];
        __syncthreads();
    }
    const float inv = rsqrtf(red[0] / (float)HID + EPSF);
    float* tr = tn + (size_t)t * HID;
    for (int c = tid * 4; c < HID; c += 1024) {
        float4 v = *(const float4*)(row + c);
        float4 sc = *(const float4*)(scale + c);
        v.x *= inv * sc.x; v.y *= inv * sc.y;
        v.z *= inv * sc.z; v.w *= inv * sc.w;
        *(float4*)(tr + c) = v;
    }
}

// ---------------------------------------------------------------------------
// up reduce (3) + bias + clamped SwiGLU -> fp32 g_act
// ---------------------------------------------------------------------------
__global__ __launch_bounds__(256) void reduce_up_act_kernel(
    const float* __restrict__ ws, const float* __restrict__ bias,
    float* __restrict__ act)
{
    const int t = blockIdx.y;
    const int j = blockIdx.x * 256 + threadIdx.x;
    if (j >= INTER / 2) return;
    const int c = j * 4;
    const size_t SL = (size_t)T_TOK * NPAD_UP;
    const float* base = ws + (size_t)t * NPAD_UP + c;
    const float4 a = *(const float4*)base;
    const float4 b = *(const float4*)(base + SL);
    const float4 d = *(const float4*)(base + 2 * SL);
    const float4 bb = *(const float4*)(bias + c);
    float u0 = a.x + b.x + d.x + bb.x;
    float u1 = a.y + b.y + d.y + bb.y;
    float u2 = a.z + b.z + d.z + bb.z;
    float u3 = a.w + b.w + d.w + bb.w;

    float g0 = fminf(u0, 7.f), l0 = fminf(fmaxf(u1, -7.f), 7.f);
    float g1 = fminf(u2, 7.f), l1 = fminf(fmaxf(u3, -7.f), 7.f);
    const float v0 = g0 / (1.f + fast_exp(-1.702f * g0)) * (l0 + 1.f);
    const float v1 = g1 / (1.f + fast_exp(-1.702f * g1)) * (l1 + 1.f);

    *(float2*)(act + (size_t)t * INTER + 2 * j) = make_float2(v0, v1);
}

// ---------------------------------------------------------------------------
// dn reduce (3) + bias + residual -> out (final)
// ---------------------------------------------------------------------------
__global__ __launch_bounds__(256) void reduce_dn_kernel(
    const float* __restrict__ ws, const float* __restrict__ bias,
    const float* __restrict__ res, float* __restrict__ C)
{
    const int idx = blockIdx.x * 256 + threadIdx.x;
    const int q = HID >> 2;
    if (idx >= T_TOK * q) return;
    const int m = idx / q;
    const int col = (idx - m * q) * 4;
    const size_t SL = (size_t)T_TOK * NPAD_DN;
    const float* p = ws + (size_t)m * NPAD_DN + col;
    const float4 a = *(const float4*)p;
    const float4 b = *(const float4*)(p + SL);
    const float4 c = *(const float4*)(p + 2 * SL);
    const float4 bb = *(const float4*)(bias + col);
    const float4 r = *(const float4*)(res + (size_t)m * HID + col);
    float4 v;
    v.x = a.x + b.x + c.x + bb.x + r.x;
    v.y = a.y + b.y + c.y + bb.y + r.y;
    v.z = a.z + b.z + c.z + bb.z + r.z;
    v.w = a.w + b.w + c.w + bb.w + r.w;
    *(float4*)(C + (size_t)m * HID + col) = v;
}

// ---------------------------------------------------------------------------
// Causal GQA flash attention, QT=64, cp.async K/V pipeline,
// warp-local softmax (shfl combine, 3 syncs/tile). fp32 output.
// ---------------------------------------------------------------------------
#define ATQ 68
#define ATV 72
#define ATTN_SMEM ((2*64*ATQ + 2*64*ATQ + 2*64*ATV + 3*64) * (int)sizeof(float))

__global__ __launch_bounds__(256) void attn_mma_kernel(
    const float* __restrict__ qkv, float* __restrict__ og)
{
    extern __shared__ float sm[];
    float* Qs   = sm;                      // 64 x ATQ
    float* Ss   = Qs + 64 * ATQ;           // 64 x ATQ
    float* Ks   = Ss + 64 * ATQ;           // 2 x 64 x ATQ
    float* Vs   = Ks + 2 * 64 * ATQ;       // 2 x 64 x ATV
    float* mrow = Vs + 2 * 64 * ATV;
    float* lrow = mrow + 64;
    float* arow = lrow + 64;

    const int qt = blockIdx.x, h = blockIdx.y, kh = h >> 3;
    const int tid = threadIdx.x, wid = tid >> 5, lane = tid & 31;
    const int wm = wid >> 2, wn = wid & 3;
    const int g = lane >> 2, qd = lane & 3;
    const int srow = tid >> 2;            // softmax row 0..63 (warp-local)
    const int part = tid & 3;             // 4 lanes per row (same warp)
    const uint32_t sbase = smem_u32(sm);
    const uint32_t kB = sbase + (2 * 64 * ATQ) * 4;
    const uint32_t vB = sbase + (2 * 64 * ATQ + 2 * 64 * ATQ) * 4;

    for (int i = tid; i < 64 * 64; i += 256) {
        int r = i >> 6, d = i & 63;
        Qs[r * ATQ + d] = tf32r(qkv[(size_t)(qt * 64 + r) * QKV_DIM + h * HD + d]);
    }
    if (tid < 64) { mrow[tid] = -1e30f; lrow[tid] = 0.f; }
    float o[2][2][4];
    #pragma unroll
    for (int i = 0; i < 2; i++)
        #pragma unroll
        for (int j = 0; j < 2; j++)
            #pragma unroll
            for (int q = 0; q < 4; q++) o[i][j][q] = 0.f;

    // prefetch tile 0
    {
        #pragma unroll
        for (int i = 0; i < 4; i++) {
            int q = tid + 256 * i;
            int r = q >> 4, c = q & 15;
            size_t base = (size_t)r * QKV_DIM;
            cp16(kB + r * (ATQ * 4) + c * 16, qkv + base + NH * HD + kh * HD + c * 4);
            cp16(vB + r * (ATV * 4) + c * 16, qkv + base + (NH + KVH) * HD + kh * HD + c * 4);
        }
        cp_commit();
    }
    __syncthreads();

    for (int kt = 0; kt <= qt; kt++) {
        const int b = kt & 1;
        if (kt + 1 <= qt) {
            const int nb = (kt + 1) & 1;
            #pragma unroll
            for (int i = 0; i < 4; i++) {
                int q = tid + 256 * i;
                int r = q >> 4, c = q & 15;
                size_t base = (size_t)((kt + 1) * 64 + r) * QKV_DIM;
                cp16(kB + (nb * 64 + r) * (ATQ * 4) + c * 16,
                     qkv + base + NH * HD + kh * HD + c * 4);
                cp16(vB + (nb * 64 + r) * (ATV * 4) + c * 16,
                     qkv + base + (NH + KVH) * HD + kh * HD + c * 4);
            }
            cp_commit();
            cp_wait1();
        } else {
            cp_wait0();
        }
        __syncthreads();

        const float* Kb = Ks + b * 64 * ATQ;
        const float* Vb = Vs + b * 64 * ATV;

        // S = Q K^T
        float s[2][2][4];
        #pragma unroll
        for (int i = 0; i < 2; i++)
            #pragma unroll
            for (int j = 0; j < 2; j++)
                #pragma unroll
                for (int q = 0; q < 4; q++) s[i][j][q] = 0.f;
        #pragma unroll
        for (int k8 = 0; k8 < 8; k8++) {
            const int k0 = k8 * 8;
            uint32_t a[2][4], bfr[2][2];
            #pragma unroll
            for (int mf = 0; mf < 2; mf++) {
                const int rb = wm * 32 + mf * 16;
                a[mf][0] = __float_as_uint(Qs[(rb + g) * ATQ + k0 + qd]);
                a[mf][1] = __float_as_uint(Qs[(rb + g + 8) * ATQ + k0 + qd]);
                a[mf][2] = __float_as_uint(Qs[(rb + g) * ATQ + k0 + 4 + qd]);
                a[mf][3] = __float_as_uint(Qs[(rb + g + 8) * ATQ + k0 + 4 + qd]);
            }
            #pragma unroll
            for (int nf = 0; nf < 2; nf++) {
                const int nb2 = wn * 16 + nf * 8;
                bfr[nf][0] = tf32u(Kb[(nb2 + g) * ATQ + k0 + qd]);
                bfr[nf][1] = tf32u(Kb[(nb2 + g) * ATQ + k0 + 4 + qd]);
            }
            #pragma unroll
            for (int mf = 0; mf < 2; mf++)
                #pragma unroll
                for (int nf = 0; nf < 2; nf++)
                    mma_tf32(s[mf][nf], a[mf], bfr[nf]);
        }
        #pragma unroll
        for (int mf = 0; mf < 2; mf++)
            #pragma unroll
            for (int nf = 0; nf < 2; nf++) {
                const int r0 = wm * 32 + mf * 16 + g;
                const int c0 = wn * 16 + nf * 8 + 2 * qd;
                *(float2*)&Ss[r0 * ATQ + c0] =
                    make_float2(s[mf][nf][0] * SM_SCALE, s[mf][nf][1] * SM_SCALE);
                *(float2*)&Ss[(r0 + 8) * ATQ + c0] =
                    make_float2(s[mf][nf][2] * SM_SCALE, s[mf][nf][3] * SM_SCALE);
            }
        __syncthreads();

        // warp-local online softmax: 4 adjacent lanes per row, shfl combine
        {
            const int cmax = (kt == qt) ? (srow + 1) : 64;
            const int c0 = part * 16;
            float mx = -1e30f;
            #pragma unroll
            for (int c = c0; c < c0 + 16; c++)
                if (c < cmax) mx = fmaxf(mx, Ss[srow * ATQ + c]);
            mx = fmaxf(mx, __shfl_xor_sync(0xFFFFFFFFu, mx, 1));
            mx = fmaxf(mx, __shfl_xor_sync(0xFFFFFFFFu, mx, 2));
            const float mold = mrow[srow];
            const float mfin = fmaxf(mold, mx);
            float sum = 0.f;
            #pragma unroll
            for (int c = c0; c < c0 + 16; c++) {
                float p = (c < cmax) ? fast_exp(Ss[srow * ATQ + c] - mfin) : 0.f;
                Ss[srow * ATQ + c] = tf32r(p);
                sum += p;
            }
            sum += __shfl_xor_sync(0xFFFFFFFFu, sum, 1);
            sum += __shfl_xor_sync(0xFFFFFFFFu, sum, 2);
            if (part == 0) {
                const float alpha = fast_exp(mold - mfin);
                mrow[srow] = mfin;
                lrow[srow] = lrow[srow] * alpha + sum;
                arow[srow] = alpha;
            }
            __syncthreads();
        }

        // O = O*alpha + P @ V
        #pragma unroll
        for (int mf = 0; mf < 2; mf++) {
            const int r0 = wm * 32 + mf * 16 + g;
            const float al0 = arow[r0], al1 = arow[r0 + 8];
            #pragma unroll
            for (int nf = 0; nf < 2; nf++) {
                o[mf][nf][0] *= al0; o[mf][nf][1] *= al0;
                o[mf][nf][2] *= al1; o[mf][nf][3] *= al1;
            }
        }
        #pragma unroll
        for (int k8 = 0; k8 < 8; k8++) {
            const int k0 = k8 * 8;
            uint32_t a[2][4], bfr[2][2];
            #pragma unroll
            for (int mf = 0; mf < 2; mf++) {
                const int rb = wm * 32 + mf * 16;
                a[mf][0] = __float_as_uint(Ss[(rb + g) * ATQ + k0 + qd]);
                a[mf][1] = __float_as_uint(Ss[(rb + g + 8) * ATQ + k0 + qd]);
                a[mf][2] = __float_as_uint(Ss[(rb + g) * ATQ + k0 + 4 + qd]);
                a[mf][3] = __float_as_uint(Ss[(rb + g + 8) * ATQ + k0 + 4 + qd]);
            }
            #pragma unroll
            for (int nf = 0; nf < 2; nf++) {
                const int nb2 = wn * 16 + nf * 8;
                bfr[nf][0] = tf32u(Vb[(k0 + qd) * ATV + nb2 + g]);
                bfr[nf][1] = tf32u(Vb[(k0 + 4 + qd) * ATV + nb2 + g]);
            }
            #pragma unroll
            for (int mf = 0; mf < 2; mf++)
                #pragma unroll
                for (int nf = 0; nf < 2; nf++)
                    mma_tf32(o[mf][nf], a[mf], bfr[nf]);
        }
        __syncthreads();
    }

    #pragma unroll
    for (int mf = 0; mf < 2; mf++) {
        const int r0 = wm * 32 + mf * 16 + g;
        const float li0 = 1.f / lrow[r0];
        const float li1 = 1.f / lrow[r0 + 8];
        #pragma unroll
        for (int nf = 0; nf < 2; nf++) {
            const int col = h * HD + wn * 16 + nf * 8 + 2 * qd;
            *(float2*)(og + (size_t)(qt * 64 + r0) * O_DIM + col) =
                make_float2(o[mf][nf][0] * li0, o[mf][nf][1] * li0);
            *(float2*)(og + (size_t)(qt * 64 + r0 + 8) * O_DIM + col) =
                make_float2(o[mf][nf][2] * li1, o[mf][nf][3] * li1);
        }
    }
}

// ---------------------------------------------------------------------------
// Launch
// ---------------------------------------------------------------------------
static inline int cdiv_i(long long a, int b) { return (int)((a + b - 1) / b); }

extern "C" void kernel_launch(void* const* d_in, const int* in_sizes, int n_in,
                              void* d_out, int out_size)
{
    const float* x        = (const float*)d_in[0];
    const float* an_scale = (const float*)d_in[1];
    const float* wqkv     = (const float*)d_in[2];
    const float* bqkv     = (const float*)d_in[3];
    const float* wout     = (const float*)d_in[4];
    const float* bout     = (const float*)d_in[5];
    const float* mn_scale = (const float*)d_in[6];
    const float* w1       = (const float*)d_in[7];
    const float* b1       = (const float*)d_in[8];
    const float* w2       = (const float*)d_in[9];
    const float* b2       = (const float*)d_in[10];
    float* out = (float*)d_out;

    static float *qkv_p = nullptr, *h_p, *t_p, *o_p, *act_p, *ws_p, *rt_p;
    if (!qkv_p) {
        cudaGetSymbolAddress((void**)&qkv_p,  g_qkv);
        cudaGetSymbolAddress((void**)&h_p,    g_h);
        cudaGetSymbolAddress((void**)&t_p,    g_t);
        cudaGetSymbolAddress((void**)&o_p,    g_o);
        cudaGetSymbolAddress((void**)&act_p,  g_act);
        cudaGetSymbolAddress((void**)&ws_p,   g_ws);
        cudaGetSymbolAddress((void**)&rt_p,   g_rope);
    }
    cudaFuncSetAttribute(attn_mma_kernel,
                         cudaFuncAttributeMaxDynamicSharedMemorySize, ATTN_SMEM);
    cudaFuncSetAttribute(tf32_gemm_sk,
                         cudaFuncAttributeMaxDynamicSharedMemorySize, GSMEM_TOTAL);

    rope_table_kernel<<<T_TOK, 32>>>(rt_p);

    // 1) attn rmsnorm -> fp32 t
    rmsnorm_kernel<<<T_TOK, 256>>>(x, an_scale, t_p);

    // 2) QKV GEMM (tf32, S=6) + fused reduce+rope
    {
        dim3 grid(T_TOK / 128, QKV_DIM / 256, 6);
        tf32_gemm_sk<<<grid, 256, GSMEM_TOTAL>>>(t_p, wqkv, ws_p,
                                                 HID, QKV_DIM, QKV_DIM, 6);
        reduce_qkv_rope_kernel<<<T_TOK, 256>>>(ws_p, bqkv, rt_p, qkv_p);
    }

    // 3) attention -> fp32 o
    {
        dim3 grid(T_TOK / 64, NH);
        attn_mma_kernel<<<grid, 256, ATTN_SMEM>>>(qkv_p, o_p);
    }

    // 4) out GEMM (tf32, S=3) + fused reduce+residual+rmsnorm
    {
        dim3 grid(T_TOK / 128, NPAD_OUT / 256, 3);
        tf32_gemm_sk<<<grid, 256, GSMEM_TOTAL>>>(o_p, wout, ws_p,
                                                 O_DIM, NPAD_OUT, HID, 3);
        reduce_out_rms_kernel<<<T_TOK, 256>>>(ws_p, bout, x, mn_scale, h_p, t_p);
    }

    // 5) MLP up GEMM (tf32, S=3) + fused reduce+act
    {
        dim3 grid(T_TOK / 128, NPAD_UP / 256, 3);
        tf32_gemm_sk<<<grid, 256, GSMEM_TOTAL>>>(t_p, w1, ws_p,
                                                 HID, NPAD_UP, U_DIM, 3);
        dim3 rg(cdiv_i(INTER / 2, 256), T_TOK);
        reduce_up_act_kernel<<<rg, 256>>>(ws_p, b1, act_p);
    }

    // 6) MLP down GEMM (tf32, S=3) + fused reduce+residual -> out
    {
        dim3 grid(T_TOK / 128, NPAD_DN / 256, 3);
        tf32_gemm_sk<<<grid, 256, GSMEM_TOTAL>>>(act_p, w2, ws_p,
                                                 INTER, NPAD_DN, HID, 3);
        reduce_dn_kernel<<<cdiv_i((long long)T_TOK * HID / 4, 256), 256>>>(
            ws_p, b2, h_p, out);
    }
}

// round 16
// speedup vs baseline: 1.0131x; 1.0131x over previous
#include <cuda_runtime.h>
#include <cuda_bf16.h>
#include <math.h>
#include <stdint.h>

// ---------------------------------------------------------------------------
// Problem constants
// ---------------------------------------------------------------------------
#define T_TOK   1024
#define HID     2880
#define NH      64
#define KVH     8
#define HD      64
#define INTER   2880
#define QKV_DIM (HD*(NH+2*KVH))      // 5120
#define O_DIM   (NH*HD)              // 4096
#define U_DIM   (2*INTER)            // 5760
#define SM_SCALE 0.125f
#define EPSF    1e-5f

#define NPAD_OUT 3072
#define NPAD_UP  5888
#define NPAD_DN  3072

// ---------------------------------------------------------------------------
// Scratch
// ---------------------------------------------------------------------------
__device__ float g_qkv[T_TOK * QKV_DIM];
__device__ float g_h  [T_TOK * HID];
__device__ float g_t  [T_TOK * HID];
__device__ float g_o  [T_TOK * O_DIM];
__device__ float g_act[T_TOK * INTER];
__device__ float g_ws [6 * T_TOK * QKV_DIM];
__device__ float g_rope[T_TOK * 64];

// ---------------------------------------------------------------------------
// PTX helpers
// ---------------------------------------------------------------------------
__device__ __forceinline__ uint32_t smem_u32(const void* p) {
    uint32_t a;
    asm("{ .reg .u64 t; cvta.to.shared.u64 t, %1; cvt.u32.u64 %0, t; }" : "=r"(a) : "l"(p));
    return a;
}
__device__ __forceinline__ void cp16(uint32_t dst, const void* src) {
    asm volatile("cp.async.cg.shared.global [%0], [%1], 16;" :: "r"(dst), "l"(src));
}
__device__ __forceinline__ void cp_commit() {
    asm volatile("cp.async.commit_group;" ::: "memory");
}
__device__ __forceinline__ void cp_wait1() {
    asm volatile("cp.async.wait_group 1;" ::: "memory");
}
__device__ __forceinline__ void cp_wait0() {
    asm volatile("cp.async.wait_group 0;" ::: "memory");
}
__device__ __forceinline__ void mma_tf32(float* c, const uint32_t* a, const uint32_t* b) {
    asm volatile("mma.sync.aligned.m16n8k8.row.col.f32.tf32.tf32.f32 "
        "{%0,%1,%2,%3}, {%4,%5,%6,%7}, {%8,%9}, {%0,%1,%2,%3};"
        : "+f"(c[0]), "+f"(c[1]), "+f"(c[2]), "+f"(c[3])
        : "r"(a[0]), "r"(a[1]), "r"(a[2]), "r"(a[3]), "r"(b[0]), "r"(b[1]));
}
__device__ __forceinline__ float tf32r(float x) {
    uint32_t o;
    asm("cvt.rna.tf32.f32 %0, %1;" : "=r"(o) : "f"(x));
    return __uint_as_float(o);
}
__device__ __forceinline__ uint32_t tf32u(float x) {
    uint32_t o;
    asm("cvt.rna.tf32.f32 %0, %1;" : "=r"(o) : "f"(x));
    return o;
}

// FMA-pipe exp
__device__ __forceinline__ float fast_exp(float x) {
    x = fmaxf(x, -80.f);
    const float y = x * 1.4426950408889634f;
    const float fn = y + 12582912.f;
    const int ni = __float_as_int(fn) - 0x4B400000;
    const float f = y - (fn - 12582912.f);
    float p = 1.3333558146e-3f;
    p = fmaf(p, f, 9.6181291076e-3f);
    p = fmaf(p, f, 5.5504108664e-2f);
    p = fmaf(p, f, 2.4022650696e-1f);
    p = fmaf(p, f, 6.9314718056e-1f);
    p = fmaf(p, f, 1.0f);
    return p * __int_as_float((ni + 127) << 23);
}

// ---------------------------------------------------------------------------
// tf32 single-pass GEMM, split-K S slices, 3-stage cp.async pipeline.
// 128x256 CTA tile, BK=32 floats. One __syncthreads per chunk.
// smem: 3 stages x (A 128x36 + B 256x36) floats = 165888 B.
// ---------------------------------------------------------------------------
#define NF32 36
#define A_F  4608
#define B_F  9216
#define STAGE_F (A_F + B_F)
#define GSMEM_TOTAL (3 * STAGE_F * 4)

__device__ __forceinline__ void fill_tiles_tf32(
    uint32_t aT, uint32_t bT,
    const float* __restrict__ A, const float* __restrict__ W,
    int K, int m0, int n0, int k0, int Nrows, int tid)
{
    #pragma unroll
    for (int i = 0; i < 4; i++) {
        int q = tid + 256 * i;
        int r = q >> 3, c = q & 7;
        cp16(aT + r * 144 + c * 16, A + (size_t)(m0 + r) * K + k0 + c * 4);
    }
    #pragma unroll
    for (int i = 0; i < 8; i++) {
        int q = tid + 256 * i;
        int r = q >> 3, c = q & 7;
        int rw = n0 + r; if (rw >= Nrows) rw = Nrows - 1;
        cp16(bT + r * 144 + c * 16, W + (size_t)rw * K + k0 + c * 4);
    }
}

__global__ __launch_bounds__(256) void tf32_gemm_sk(
    const float* __restrict__ A, const float* __restrict__ W,
    float* __restrict__ ws, int K, int Npad, int Nrows, int S)
{
    extern __shared__ char smem[];
    const uint32_t sbase = smem_u32(smem);
    float* smf = (float*)smem;

    const int tid  = threadIdx.x;
    const int wid  = tid >> 5;
    const int lane = tid & 31;
    const int wm   = wid >> 2;
    const int wn   = wid & 3;
    const int g    = lane >> 2;
    const int qd   = lane & 3;
    const int m0 = blockIdx.x * 128;
    const int n0 = blockIdx.y * 256;
    const int z  = blockIdx.z;
    const int NC = K >> 5;
    const int cb = (z * NC) / S;
    const int ce = ((z + 1) * NC) / S;

    float acc[4][8][4];
    #pragma unroll
    for (int i = 0; i < 4; i++)
        #pragma unroll
        for (int j = 0; j < 8; j++)
            #pragma unroll
            for (int q = 0; q < 4; q++) acc[i][j][q] = 0.f;

    // prologue: stages for chunks cb, cb+1
    {
        const uint32_t s0 = sbase;                       // stage 0
        fill_tiles_tf32(s0, s0 + A_F * 4, A, W, K, m0, n0, cb << 5, Nrows, tid);
        cp_commit();
        if (cb + 1 < ce) {
            const uint32_t s1 = sbase + STAGE_F * 4;     // stage 1
            fill_tiles_tf32(s1, s1 + A_F * 4, A, W, K, m0, n0,
                            (cb + 1) << 5, Nrows, tid);
            cp_commit();
        }
    }

    for (int c = cb; c < ce; c++) {
        if (c + 1 < ce) cp_wait1(); else cp_wait0();
        __syncthreads();

        if (c + 2 < ce) {
            const int st = (c + 2 - cb) % 3;
            const uint32_t sp = sbase + st * STAGE_F * 4;
            fill_tiles_tf32(sp, sp + A_F * 4, A, W, K, m0, n0,
                            (c + 2) << 5, Nrows, tid);
            cp_commit();
        }

        const int bs = (c - cb) % 3;
        const float* As = smf + bs * STAGE_F;
        const float* Bs = As + A_F;

        #pragma unroll
        for (int ks = 0; ks < 4; ks++) {
            const int k0 = ks * 8;
            uint32_t a[4][4], bb[8][2];
            #pragma unroll
            for (int mf = 0; mf < 4; mf++) {
                const int row = wm * 64 + mf * 16 + g;
                a[mf][0] = tf32u(As[row * NF32 + k0 + qd]);
                a[mf][1] = tf32u(As[(row + 8) * NF32 + k0 + qd]);
                a[mf][2] = tf32u(As[row * NF32 + k0 + 4 + qd]);
                a[mf][3] = tf32u(As[(row + 8) * NF32 + k0 + 4 + qd]);
            }
            #pragma unroll
            for (int nf = 0; nf < 8; nf++) {
                const int rowb = wn * 64 + nf * 8 + g;
                bb[nf][0] = tf32u(Bs[rowb * NF32 + k0 + qd]);
                bb[nf][1] = tf32u(Bs[rowb * NF32 + k0 + 4 + qd]);
            }
            #pragma unroll
            for (int mf = 0; mf < 4; mf++)
                #pragma unroll
                for (int nf = 0; nf < 8; nf++)
                    mma_tf32(acc[mf][nf], a[mf], bb[nf]);
        }
    }

    float* wz = ws + (size_t)z * T_TOK * Npad;
    const int t = lane & 3;
    #pragma unroll
    for (int nf = 0; nf < 8; nf++) {
        const int col = n0 + wn * 64 + nf * 8 + t * 2;
        #pragma unroll
        for (int mf = 0; mf < 4; mf++) {
            const int r0 = m0 + wm * 64 + mf * 16 + g;
            *(float2*)(wz + (size_t)r0 * Npad + col) =
                make_float2(acc[mf][nf][0], acc[mf][nf][1]);
            *(float2*)(wz + (size_t)(r0 + 8) * Npad + col) =
                make_float2(acc[mf][nf][2], acc[mf][nf][3]);
        }
    }
}

// ---------------------------------------------------------------------------
// Rope table
// ---------------------------------------------------------------------------
__global__ void rope_table_kernel(float* __restrict__ tab)
{
    const int t = blockIdx.x;
    const int i = threadIdx.x;
    const float PI = 3.14159265358979323846f;
    const float rope_base = 150000.f;
    const float freq = powf(rope_base, (float)i / 32.f);
    const float conc = 0.1f * logf(32.f) + 1.f;
    const float lg = logf(rope_base);
    const float low  = 32.f * logf(4096.f / (32.f * 2.f * PI)) / lg;
    const float high = 32.f * logf(4096.f / (2.f * PI)) / lg;
    const float interp = 1.f / (32.f * freq);
    const float extrap = 1.f / freq;
    float ramp = ((float)i - low) / (high - low);
    ramp = fminf(fmaxf(ramp, 0.f), 1.f);
    const float mask = 1.f - ramp;
    const float invf = interp * (1.f - mask) + extrap * mask;
    const float ang = (float)t * invf;
    tab[t * 64 + i]      = cosf(ang) * conc;
    tab[t * 64 + 32 + i] = sinf(ang) * conc;
}

// ---------------------------------------------------------------------------
// RMSNorm (plain fp32 output)
// ---------------------------------------------------------------------------
__global__ __launch_bounds__(256) void rmsnorm_kernel(
    const float* __restrict__ x, const float* __restrict__ scale,
    float* __restrict__ out)
{
    const int row = blockIdx.x;
    const float* xr = x + (size_t)row * HID;
    float s = 0.f;
    for (int i = threadIdx.x; i < HID; i += 256) { float v = xr[i]; s += v * v; }
    __shared__ float red[256];
    red[threadIdx.x] = s;
    __syncthreads();
    for (int off = 128; off > 0; off >>= 1) {
        if (threadIdx.x < off) red[threadIdx.x] += red[threadIdx.x + off];
        __syncthreads();
    }
    const float inv = rsqrtf(red[0] / (float)HID + EPSF);
    float* orow = out + (size_t)row * HID;
    for (int i = threadIdx.x; i < HID; i += 256)
        orow[i] = xr[i] * inv * scale[i];
}

// ---------------------------------------------------------------------------
// QKV reduce (6 slices) + bias + RoPE -> qkv
// ---------------------------------------------------------------------------
__global__ __launch_bounds__(256) void reduce_qkv_rope_kernel(
    const float* __restrict__ ws, const float* __restrict__ bias,
    const float* __restrict__ tab, float* __restrict__ qkv)
{
    const int t = blockIdx.x;
    const int tid = threadIdx.x;
    const size_t SL = (size_t)T_TOK * QKV_DIM;
    const float* base = ws + (size_t)t * QKV_DIM;
    float* outr = qkv + (size_t)t * QKV_DIM;
    const float* tr = tab + t * 64;

    for (int p = tid; p < 72 * 32; p += 256) {
        const int head = p >> 5, d = p & 31;
        const int c1 = head * 64 + d, c2 = c1 + 32;
        float s1 = bias[c1], s2 = bias[c2];
        #pragma unroll
        for (int z = 0; z < 6; z++) {
            s1 += base[z * SL + c1];
            s2 += base[z * SL + c2];
        }
        const float cc = tr[d], ss = tr[32 + d];
        outr[c1] = s1 * cc - s2 * ss;
        outr[c2] = s2 * cc + s1 * ss;
    }
    for (int c = 4608 + tid; c < QKV_DIM; c += 256) {
        float s = bias[c];
        #pragma unroll
        for (int z = 0; z < 6; z++) s += base[z * SL + c];
        outr[c] = s;
    }
}

// ---------------------------------------------------------------------------
// out reduce (3) + bias + residual -> h, then rmsnorm -> fp32 g_t
// ---------------------------------------------------------------------------
__global__ __launch_bounds__(256) void reduce_out_rms_kernel(
    const float* __restrict__ ws, const float* __restrict__ bias,
    const float* __restrict__ res, const float* __restrict__ scale,
    float* __restrict__ h, float* __restrict__ tn)
{
    __shared__ float row[HID];
    __shared__ float red[256];
    const int t = blockIdx.x;
    const int tid = threadIdx.x;
    const size_t SL = (size_t)T_TOK * NPAD_OUT;
    const float* base = ws + (size_t)t * NPAD_OUT;
    const float* xr = res + (size_t)t * HID;
    float* hr = h + (size_t)t * HID;

    float sq = 0.f;
    for (int c = tid * 4; c < HID; c += 1024) {
        const float4 a = *(const float4*)(base + c);
        const float4 b = *(const float4*)(base + SL + c);
        const float4 d = *(const float4*)(base + 2 * SL + c);
        const float4 bb = *(const float4*)(bias + c);
        const float4 rv = *(const float4*)(xr + c);
        float4 v;
        v.x = a.x + b.x + d.x + bb.x + rv.x;
        v.y = a.y + b.y + d.y + bb.y + rv.y;
        v.z = a.z + b.z + d.z + bb.z + rv.z;
        v.w = a.w + b.w + d.w + bb.w + rv.w;
        *(float4*)(row + c) = v;
        *(float4*)(hr + c) = v;
        sq += v.x * v.x + v.y * v.y + v.z * v.z + v.w * v.w;
    }
    red[tid] = sq;
    __syncthreads();
    for (int off = 128; off > 0; off >>= 1) {
        if (tid < off) red[tid] += red[tid + off];
        __syncthreads();
    }
    const float inv = rsqrtf(red[0] / (float)HID + EPSF);
    float* tr = tn + (size_t)t * HID;
    for (int c = tid * 4; c < HID; c += 1024) {
        float4 v = *(const float4*)(row + c);
        float4 sc = *(const float4*)(scale + c);
        v.x *= inv * sc.x; v.y *= inv * sc.y;
        v.z *= inv * sc.z; v.w *= inv * sc.w;
        *(float4*)(tr + c) = v;
    }
}

// ---------------------------------------------------------------------------
// up reduce (3) + bias + clamped SwiGLU -> fp32 g_act
// ---------------------------------------------------------------------------
__global__ __launch_bounds__(256) void reduce_up_act_kernel(
    const float* __restrict__ ws, const float* __restrict__ bias,
    float* __restrict__ act)
{
    const int t = blockIdx.y;
    const int j = blockIdx.x * 256 + threadIdx.x;
    if (j >= INTER / 2) return;
    const int c = j * 4;
    const size_t SL = (size_t)T_TOK * NPAD_UP;
    const float* base = ws + (size_t)t * NPAD_UP + c;
    const float4 a = *(const float4*)base;
    const float4 b = *(const float4*)(base + SL);
    const float4 d = *(const float4*)(base + 2 * SL);
    const float4 bb = *(const float4*)(bias + c);
    float u0 = a.x + b.x + d.x + bb.x;
    float u1 = a.y + b.y + d.y + bb.y;
    float u2 = a.z + b.z + d.z + bb.z;
    float u3 = a.w + b.w + d.w + bb.w;

    float g0 = fminf(u0, 7.f), l0 = fminf(fmaxf(u1, -7.f), 7.f);
    float g1 = fminf(u2, 7.f), l1 = fminf(fmaxf(u3, -7.f), 7.f);
    const float v0 = g0 / (1.f + fast_exp(-1.702f * g0)) * (l0 + 1.f);
    const float v1 = g1 / (1.f + fast_exp(-1.702f * g1)) * (l1 + 1.f);

    *(float2*)(act + (size_t)t * INTER + 2 * j) = make_float2(v0, v1);
}

// ---------------------------------------------------------------------------
// dn reduce (3) + bias + residual -> out (final)
// ---------------------------------------------------------------------------
__global__ __launch_bounds__(256) void reduce_dn_kernel(
    const float* __restrict__ ws, const float* __restrict__ bias,
    const float* __restrict__ res, float* __restrict__ C)
{
    const int idx = blockIdx.x * 256 + threadIdx.x;
    const int q = HID >> 2;
    if (idx >= T_TOK * q) return;
    const int m = idx / q;
    const int col = (idx - m * q) * 4;
    const size_t SL = (size_t)T_TOK * NPAD_DN;
    const float* p = ws + (size_t)m * NPAD_DN + col;
    const float4 a = *(const float4*)p;
    const float4 b = *(const float4*)(p + SL);
    const float4 c = *(const float4*)(p + 2 * SL);
    const float4 bb = *(const float4*)(bias + col);
    const float4 r = *(const float4*)(res + (size_t)m * HID + col);
    float4 v;
    v.x = a.x + b.x + c.x + bb.x + r.x;
    v.y = a.y + b.y + c.y + bb.y + r.y;
    v.z = a.z + b.z + c.z + bb.z + r.z;
    v.w = a.w + b.w + c.w + bb.w + r.w;
    *(float4*)(C + (size_t)m * HID + col) = v;
}

// ---------------------------------------------------------------------------
// Causal GQA flash attention, QT=64, cp.async K/V pipeline,
// warp-local softmax (shfl combine). fp32 output. (round-14, kept)
// ---------------------------------------------------------------------------
#define ATQ 68
#define ATV 72
#define ATTN_SMEM ((2*64*ATQ + 2*64*ATQ + 2*64*ATV + 3*64) * (int)sizeof(float))

__global__ __launch_bounds__(256) void attn_mma_kernel(
    const float* __restrict__ qkv, float* __restrict__ og)
{
    extern __shared__ float sm[];
    float* Qs   = sm;
    float* Ss   = Qs + 64 * ATQ;
    float* Ks   = Ss + 64 * ATQ;
    float* Vs   = Ks + 2 * 64 * ATQ;
    float* mrow = Vs + 2 * 64 * ATV;
    float* lrow = mrow + 64;
    float* arow = lrow + 64;

    const int qt = blockIdx.x, h = blockIdx.y, kh = h >> 3;
    const int tid = threadIdx.x, wid = tid >> 5, lane = tid & 31;
    const int wm = wid >> 2, wn = wid & 3;
    const int g = lane >> 2, qd = lane & 3;
    const int srow = tid >> 2;
    const int part = tid & 3;
    const uint32_t sbase = smem_u32(sm);
    const uint32_t kB = sbase + (2 * 64 * ATQ) * 4;
    const uint32_t vB = sbase + (2 * 64 * ATQ + 2 * 64 * ATQ) * 4;

    for (int i = tid; i < 64 * 64; i += 256) {
        int r = i >> 6, d = i & 63;
        Qs[r * ATQ + d] = tf32r(qkv[(size_t)(qt * 64 + r) * QKV_DIM + h * HD + d]);
    }
    if (tid < 64) { mrow[tid] = -1e30f; lrow[tid] = 0.f; }
    float o[2][2][4];
    #pragma unroll
    for (int i = 0; i < 2; i++)
        #pragma unroll
        for (int j = 0; j < 2; j++)
            #pragma unroll
            for (int q = 0; q < 4; q++) o[i][j][q] = 0.f;

    {
        #pragma unroll
        for (int i = 0; i < 4; i++) {
            int q = tid + 256 * i;
            int r = q >> 4, c = q & 15;
            size_t base = (size_t)r * QKV_DIM;
            cp16(kB + r * (ATQ * 4) + c * 16, qkv + base + NH * HD + kh * HD + c * 4);
            cp16(vB + r * (ATV * 4) + c * 16, qkv + base + (NH + KVH) * HD + kh * HD + c * 4);
        }
        cp_commit();
    }
    __syncthreads();

    for (int kt = 0; kt <= qt; kt++) {
        const int b = kt & 1;
        if (kt + 1 <= qt) {
            const int nb = (kt + 1) & 1;
            #pragma unroll
            for (int i = 0; i < 4; i++) {
                int q = tid + 256 * i;
                int r = q >> 4, c = q & 15;
                size_t base = (size_t)((kt + 1) * 64 + r) * QKV_DIM;
                cp16(kB + (nb * 64 + r) * (ATQ * 4) + c * 16,
                     qkv + base + NH * HD + kh * HD + c * 4);
                cp16(vB + (nb * 64 + r) * (ATV * 4) + c * 16,
                     qkv + base + (NH + KVH) * HD + kh * HD + c * 4);
            }
            cp_commit();
            cp_wait1();
        } else {
            cp_wait0();
        }
        __syncthreads();

        const float* Kb = Ks + b * 64 * ATQ;
        const float* Vb = Vs + b * 64 * ATV;

        float s[2][2][4];
        #pragma unroll
        for (int i = 0; i < 2; i++)
            #pragma unroll
            for (int j = 0; j < 2; j++)
                #pragma unroll
                for (int q = 0; q < 4; q++) s[i][j][q] = 0.f;
        #pragma unroll
        for (int k8 = 0; k8 < 8; k8++) {
            const int k0 = k8 * 8;
            uint32_t a[2][4], bfr[2][2];
            #pragma unroll
            for (int mf = 0; mf < 2; mf++) {
                const int rb = wm * 32 + mf * 16;
                a[mf][0] = __float_as_uint(Qs[(rb + g) * ATQ + k0 + qd]);
                a[mf][1] = __float_as_uint(Qs[(rb + g + 8) * ATQ + k0 + qd]);
                a[mf][2] = __float_as_uint(Qs[(rb + g) * ATQ + k0 + 4 + qd]);
                a[mf][3] = __float_as_uint(Qs[(rb + g + 8) * ATQ + k0 + 4 + qd]);
            }
            #pragma unroll
            for (int nf = 0; nf < 2; nf++) {
                const int nb2 = wn * 16 + nf * 8;
                bfr[nf][0] = tf32u(Kb[(nb2 + g) * ATQ + k0 + qd]);
                bfr[nf][1] = tf32u(Kb[(nb2 + g) * ATQ + k0 + 4 + qd]);
            }
            #pragma unroll
            for (int mf = 0; mf < 2; mf++)
                #pragma unroll
                for (int nf = 0; nf < 2; nf++)
                    mma_tf32(s[mf][nf], a[mf], bfr[nf]);
        }
        #pragma unroll
        for (int mf = 0; mf < 2; mf++)
            #pragma unroll
            for (int nf = 0; nf < 2; nf++) {
                const int r0 = wm * 32 + mf * 16 + g;
                const int c0 = wn * 16 + nf * 8 + 2 * qd;
                *(float2*)&Ss[r0 * ATQ + c0] =
                    make_float2(s[mf][nf][0] * SM_SCALE, s[mf][nf][1] * SM_SCALE);
                *(float2*)&Ss[(r0 + 8) * ATQ + c0] =
                    make_float2(s[mf][nf][2] * SM_SCALE, s[mf][nf][3] * SM_SCALE);
            }
        __syncthreads();

        {
            const int cmax = (kt == qt) ? (srow + 1) : 64;
            const int c0 = part * 16;
            float mx = -1e30f;
            #pragma unroll
            for (int c = c0; c < c0 + 16; c++)
                if (c < cmax) mx = fmaxf(mx, Ss[srow * ATQ + c]);
            mx = fmaxf(mx, __shfl_xor_sync(0xFFFFFFFFu, mx, 1));
            mx = fmaxf(mx, __shfl_xor_sync(0xFFFFFFFFu, mx, 2));
            const float mold = mrow[srow];
            const float mfin = fmaxf(mold, mx);
            float sum = 0.f;
            #pragma unroll
            for (int c = c0; c < c0 + 16; c++) {
                float p = (c < cmax) ? fast_exp(Ss[srow * ATQ + c] - mfin) : 0.f;
                Ss[srow * ATQ + c] = tf32r(p);
                sum += p;
            }
            sum += __shfl_xor_sync(0xFFFFFFFFu, sum, 1);
            sum += __shfl_xor_sync(0xFFFFFFFFu, sum, 2);
            if (part == 0) {
                const float alpha = fast_exp(mold - mfin);
                mrow[srow] = mfin;
                lrow[srow] = lrow[srow] * alpha + sum;
                arow[srow] = alpha;
            }
            __syncthreads();
        }

        #pragma unroll
        for (int mf = 0; mf < 2; mf++) {
            const int r0 = wm * 32 + mf * 16 + g;
            const float al0 = arow[r0], al1 = arow[r0 + 8];
            #pragma unroll
            for (int nf = 0; nf < 2; nf++) {
                o[mf][nf][0] *= al0; o[mf][nf][1] *= al0;
                o[mf][nf][2] *= al1; o[mf][nf][3] *= al1;
            }
        }
        #pragma unroll
        for (int k8 = 0; k8 < 8; k8++) {
            const int k0 = k8 * 8;
            uint32_t a[2][4], bfr[2][2];
            #pragma unroll
            for (int mf = 0; mf < 2; mf++) {
                const int rb = wm * 32 + mf * 16;
                a[mf][0] = __float_as_uint(Ss[(rb + g) * ATQ + k0 + qd]);
                a[mf][1] = __float_as_uint(Ss[(rb + g + 8) * ATQ + k0 + qd]);
                a[mf][2] = __float_as_uint(Ss[(rb + g) * ATQ + k0 + 4 + qd]);
                a[mf][3] = __float_as_uint(Ss[(rb + g + 8) * ATQ + k0 + 4 + qd]);
            }
            #pragma unroll
            for (int nf = 0; nf < 2; nf++) {
                const int nb2 = wn * 16 + nf * 8;
                bfr[nf][0] = tf32u(Vb[(k0 + qd) * ATV + nb2 + g]);
                bfr[nf][1] = tf32u(Vb[(k0 + 4 + qd) * ATV + nb2 + g]);
            }
            #pragma unroll
            for (int mf = 0; mf < 2; mf++)
                #pragma unroll
                for (int nf = 0; nf < 2; nf++)
                    mma_tf32(o[mf][nf], a[mf], bfr[nf]);
        }
        __syncthreads();
    }

    #pragma unroll
    for (int mf = 0; mf < 2; mf++) {
        const int r0 = wm * 32 + mf * 16 + g;
        const float li0 = 1.f / lrow[r0];
        const float li1 = 1.f / lrow[r0 + 8];
        #pragma unroll
        for (int nf = 0; nf < 2; nf++) {
            const int col = h * HD + wn * 16 + nf * 8 + 2 * qd;
            *(float2*)(og + (size_t)(qt * 64 + r0) * O_DIM + col) =
                make_float2(o[mf][nf][0] * li0, o[mf][nf][1] * li0);
            *(float2*)(og + (size_t)(qt * 64 + r0 + 8) * O_DIM + col) =
                make_float2(o[mf][nf][2] * li1, o[mf][nf][3] * li1);
        }
    }
}

// ---------------------------------------------------------------------------
// Launch
// ---------------------------------------------------------------------------
static inline int cdiv_i(long long a, int b) { return (int)((a + b - 1) / b); }

extern "C" void kernel_launch(void* const* d_in, const int* in_sizes, int n_in,
                              void* d_out, int out_size)
{
    const float* x        = (const float*)d_in[0];
    const float* an_scale = (const float*)d_in[1];
    const float* wqkv     = (const float*)d_in[2];
    const float* bqkv     = (const float*)d_in[3];
    const float* wout     = (const float*)d_in[4];
    const float* bout     = (const float*)d_in[5];
    const float* mn_scale = (const float*)d_in[6];
    const float* w1       = (const float*)d_in[7];
    const float* b1       = (const float*)d_in[8];
    const float* w2       = (const float*)d_in[9];
    const float* b2       = (const float*)d_in[10];
    float* out = (float*)d_out;

    static float *qkv_p = nullptr, *h_p, *t_p, *o_p, *act_p, *ws_p, *rt_p;
    if (!qkv_p) {
        cudaGetSymbolAddress((void**)&qkv_p,  g_qkv);
        cudaGetSymbolAddress((void**)&h_p,    g_h);
        cudaGetSymbolAddress((void**)&t_p,    g_t);
        cudaGetSymbolAddress((void**)&o_p,    g_o);
        cudaGetSymbolAddress((void**)&act_p,  g_act);
        cudaGetSymbolAddress((void**)&ws_p,   g_ws);
        cudaGetSymbolAddress((void**)&rt_p,   g_rope);
    }
    cudaFuncSetAttribute(attn_mma_kernel,
                         cudaFuncAttributeMaxDynamicSharedMemorySize, ATTN_SMEM);
    cudaFuncSetAttribute(tf32_gemm_sk,
                         cudaFuncAttributeMaxDynamicSharedMemorySize, GSMEM_TOTAL);

    rope_table_kernel<<<T_TOK, 32>>>(rt_p);

    // 1) attn rmsnorm -> fp32 t
    rmsnorm_kernel<<<T_TOK, 256>>>(x, an_scale, t_p);

    // 2) QKV GEMM (tf32, S=6) + fused reduce+rope
    {
        dim3 grid(T_TOK / 128, QKV_DIM / 256, 6);
        tf32_gemm_sk<<<grid, 256, GSMEM_TOTAL>>>(t_p, wqkv, ws_p,
                                                 HID, QKV_DIM, QKV_DIM, 6);
        reduce_qkv_rope_kernel<<<T_TOK, 256>>>(ws_p, bqkv, rt_p, qkv_p);
    }

    // 3) attention -> fp32 o
    {
        dim3 grid(T_TOK / 64, NH);
        attn_mma_kernel<<<grid, 256, ATTN_SMEM>>>(qkv_p, o_p);
    }

    // 4) out GEMM (tf32, S=3) + fused reduce+residual+rmsnorm
    {
        dim3 grid(T_TOK / 128, NPAD_OUT / 256, 3);
        tf32_gemm_sk<<<grid, 256, GSMEM_TOTAL>>>(o_p, wout, ws_p,
                                                 O_DIM, NPAD_OUT, HID, 3);
        reduce_out_rms_kernel<<<T_TOK, 256>>>(ws_p, bout, x, mn_scale, h_p, t_p);
    }

    // 5) MLP up GEMM (tf32, S=3) + fused reduce+act
    {
        dim3 grid(T_TOK / 128, NPAD_UP / 256, 3);
        tf32_gemm_sk<<<grid, 256, GSMEM_TOTAL>>>(t_p, w1, ws_p,
                                                 HID, NPAD_UP, U_DIM, 3);
        dim3 rg(cdiv_i(INTER / 2, 256), T_TOK);
        reduce_up_act_kernel<<<rg, 256>>>(ws_p, b1, act_p);
    }

    // 6) MLP down GEMM (tf32, S=3) + fused reduce+residual -> out
    {
        dim3 grid(T_TOK / 128, NPAD_DN / 256, 3);
        tf32_gemm_sk<<<grid, 256, GSMEM_TOTAL>>>(act_p, w2, ws_p,
                                                 INTER, NPAD_DN, HID, 3);
        reduce_dn_kernel<<<cdiv_i((long long)T_TOK * HID / 4, 256), 256>>>(
            ws_p, b2, h_p, out);
    }
}

// round 17
// speedup vs baseline: 1.0135x; 1.0004x over previous
#include <cuda_runtime.h>
#include <cuda_bf16.h>
#include <math.h>
#include <stdint.h>

// ---------------------------------------------------------------------------
// Problem constants
// ---------------------------------------------------------------------------
#define T_TOK   1024
#define HID     2880
#define NH      64
#define KVH     8
#define HD      64
#define INTER   2880
#define QKV_DIM (HD*(NH+2*KVH))      // 5120
#define O_DIM   (NH*HD)              // 4096
#define U_DIM   (2*INTER)            // 5760
#define SM_SCALE 0.125f
#define EPSF    1e-5f

#define NPAD_OUT 3072
#define NPAD_UP  5888
#define NPAD_DN  3072

// ---------------------------------------------------------------------------
// Scratch
// ---------------------------------------------------------------------------
__device__ float g_qkv[T_TOK * QKV_DIM];
__device__ float g_h  [T_TOK * HID];
__device__ float g_t  [T_TOK * HID];
__device__ float g_o  [T_TOK * O_DIM];
__device__ float g_act[T_TOK * INTER];
__device__ float g_ws [6 * T_TOK * QKV_DIM];
__device__ float g_rope[T_TOK * 64];

// ---------------------------------------------------------------------------
// PTX helpers
// ---------------------------------------------------------------------------
__device__ __forceinline__ uint32_t smem_u32(const void* p) {
    uint32_t a;
    asm("{ .reg .u64 t; cvta.to.shared.u64 t, %1; cvt.u32.u64 %0, t; }" : "=r"(a) : "l"(p));
    return a;
}
__device__ __forceinline__ void cp16(uint32_t dst, const void* src) {
    asm volatile("cp.async.cg.shared.global [%0], [%1], 16;" :: "r"(dst), "l"(src));
}
__device__ __forceinline__ void cp_commit() {
    asm volatile("cp.async.commit_group;" ::: "memory");
}
__device__ __forceinline__ void cp_wait1() {
    asm volatile("cp.async.wait_group 1;" ::: "memory");
}
__device__ __forceinline__ void cp_wait0() {
    asm volatile("cp.async.wait_group 0;" ::: "memory");
}
__device__ __forceinline__ void mma_tf32(float* c, const uint32_t* a, const uint32_t* b) {
    asm volatile("mma.sync.aligned.m16n8k8.row.col.f32.tf32.tf32.f32 "
        "{%0,%1,%2,%3}, {%4,%5,%6,%7}, {%8,%9}, {%0,%1,%2,%3};"
        : "+f"(c[0]), "+f"(c[1]), "+f"(c[2]), "+f"(c[3])
        : "r"(a[0]), "r"(a[1]), "r"(a[2]), "r"(a[3]), "r"(b[0]), "r"(b[1]));
}
__device__ __forceinline__ float tf32r(float x) {
    uint32_t o;
    asm("cvt.rna.tf32.f32 %0, %1;" : "=r"(o) : "f"(x));
    return __uint_as_float(o);
}
__device__ __forceinline__ uint32_t tf32u(float x) {
    uint32_t o;
    asm("cvt.rna.tf32.f32 %0, %1;" : "=r"(o) : "f"(x));
    return o;
}

// FMA-pipe exp
__device__ __forceinline__ float fast_exp(float x) {
    x = fmaxf(x, -80.f);
    const float y = x * 1.4426950408889634f;
    const float fn = y + 12582912.f;
    const int ni = __float_as_int(fn) - 0x4B400000;
    const float f = y - (fn - 12582912.f);
    float p = 1.3333558146e-3f;
    p = fmaf(p, f, 9.6181291076e-3f);
    p = fmaf(p, f, 5.5504108664e-2f);
    p = fmaf(p, f, 2.4022650696e-1f);
    p = fmaf(p, f, 6.9314718056e-1f);
    p = fmaf(p, f, 1.0f);
    return p * __int_as_float((ni + 127) << 23);
}

// ---------------------------------------------------------------------------
// tf32 single-pass GEMM, split-K S slices, 3-stage cp.async pipeline.
// ---------------------------------------------------------------------------
#define NF32 36
#define A_F  4608
#define B_F  9216
#define STAGE_F (A_F + B_F)
#define GSMEM_TOTAL (3 * STAGE_F * 4)

__device__ __forceinline__ void fill_tiles_tf32(
    uint32_t aT, uint32_t bT,
    const float* __restrict__ A, const float* __restrict__ W,
    int K, int m0, int n0, int k0, int Nrows, int tid)
{
    #pragma unroll
    for (int i = 0; i < 4; i++) {
        int q = tid + 256 * i;
        int r = q >> 3, c = q & 7;
        cp16(aT + r * 144 + c * 16, A + (size_t)(m0 + r) * K + k0 + c * 4);
    }
    #pragma unroll
    for (int i = 0; i < 8; i++) {
        int q = tid + 256 * i;
        int r = q >> 3, c = q & 7;
        int rw = n0 + r; if (rw >= Nrows) rw = Nrows - 1;
        cp16(bT + r * 144 + c * 16, W + (size_t)rw * K + k0 + c * 4);
    }
}

__global__ __launch_bounds__(256) void tf32_gemm_sk(
    const float* __restrict__ A, const float* __restrict__ W,
    float* __restrict__ ws, int K, int Npad, int Nrows, int S)
{
    extern __shared__ char smem[];
    const uint32_t sbase = smem_u32(smem);
    float* smf = (float*)smem;

    const int tid  = threadIdx.x;
    const int wid  = tid >> 5;
    const int lane = tid & 31;
    const int wm   = wid >> 2;
    const int wn   = wid & 3;
    const int g    = lane >> 2;
    const int qd   = lane & 3;
    const int m0 = blockIdx.x * 128;
    const int n0 = blockIdx.y * 256;
    const int z  = blockIdx.z;
    const int NC = K >> 5;
    const int cb = (z * NC) / S;
    const int ce = ((z + 1) * NC) / S;

    float acc[4][8][4];
    #pragma unroll
    for (int i = 0; i < 4; i++)
        #pragma unroll
        for (int j = 0; j < 8; j++)
            #pragma unroll
            for (int q = 0; q < 4; q++) acc[i][j][q] = 0.f;

    {
        const uint32_t s0 = sbase;
        fill_tiles_tf32(s0, s0 + A_F * 4, A, W, K, m0, n0, cb << 5, Nrows, tid);
        cp_commit();
        if (cb + 1 < ce) {
            const uint32_t s1 = sbase + STAGE_F * 4;
            fill_tiles_tf32(s1, s1 + A_F * 4, A, W, K, m0, n0,
                            (cb + 1) << 5, Nrows, tid);
            cp_commit();
        }
    }

    for (int c = cb; c < ce; c++) {
        if (c + 1 < ce) cp_wait1(); else cp_wait0();
        __syncthreads();

        if (c + 2 < ce) {
            const int st = (c + 2 - cb) % 3;
            const uint32_t sp = sbase + st * STAGE_F * 4;
            fill_tiles_tf32(sp, sp + A_F * 4, A, W, K, m0, n0,
                            (c + 2) << 5, Nrows, tid);
            cp_commit();
        }

        const int bs = (c - cb) % 3;
        const float* As = smf + bs * STAGE_F;
        const float* Bs = As + A_F;

        #pragma unroll
        for (int ks = 0; ks < 4; ks++) {
            const int k0 = ks * 8;
            uint32_t a[4][4], bb[8][2];
            #pragma unroll
            for (int mf = 0; mf < 4; mf++) {
                const int row = wm * 64 + mf * 16 + g;
                a[mf][0] = tf32u(As[row * NF32 + k0 + qd]);
                a[mf][1] = tf32u(As[(row + 8) * NF32 + k0 + qd]);
                a[mf][2] = tf32u(As[row * NF32 + k0 + 4 + qd]);
                a[mf][3] = tf32u(As[(row + 8) * NF32 + k0 + 4 + qd]);
            }
            #pragma unroll
            for (int nf = 0; nf < 8; nf++) {
                const int rowb = wn * 64 + nf * 8 + g;
                bb[nf][0] = tf32u(Bs[rowb * NF32 + k0 + qd]);
                bb[nf][1] = tf32u(Bs[rowb * NF32 + k0 + 4 + qd]);
            }
            #pragma unroll
            for (int mf = 0; mf < 4; mf++)
                #pragma unroll
                for (int nf = 0; nf < 8; nf++)
                    mma_tf32(acc[mf][nf], a[mf], bb[nf]);
        }
    }

    float* wz = ws + (size_t)z * T_TOK * Npad;
    const int t = lane & 3;
    #pragma unroll
    for (int nf = 0; nf < 8; nf++) {
        const int col = n0 + wn * 64 + nf * 8 + t * 2;
        #pragma unroll
        for (int mf = 0; mf < 4; mf++) {
            const int r0 = m0 + wm * 64 + mf * 16 + g;
            *(float2*)(wz + (size_t)r0 * Npad + col) =
                make_float2(acc[mf][nf][0], acc[mf][nf][1]);
            *(float2*)(wz + (size_t)(r0 + 8) * Npad + col) =
                make_float2(acc[mf][nf][2], acc[mf][nf][3]);
        }
    }
}

// ---------------------------------------------------------------------------
// Rope table
// ---------------------------------------------------------------------------
__global__ void rope_table_kernel(float* __restrict__ tab)
{
    const int t = blockIdx.x;
    const int i = threadIdx.x;
    const float PI = 3.14159265358979323846f;
    const float rope_base = 150000.f;
    const float freq = powf(rope_base, (float)i / 32.f);
    const float conc = 0.1f * logf(32.f) + 1.f;
    const float lg = logf(rope_base);
    const float low  = 32.f * logf(4096.f / (32.f * 2.f * PI)) / lg;
    const float high = 32.f * logf(4096.f / (2.f * PI)) / lg;
    const float interp = 1.f / (32.f * freq);
    const float extrap = 1.f / freq;
    float ramp = ((float)i - low) / (high - low);
    ramp = fminf(fmaxf(ramp, 0.f), 1.f);
    const float mask = 1.f - ramp;
    const float invf = interp * (1.f - mask) + extrap * mask;
    const float ang = (float)t * invf;
    tab[t * 64 + i]      = cosf(ang) * conc;
    tab[t * 64 + 32 + i] = sinf(ang) * conc;
}

// ---------------------------------------------------------------------------
// RMSNorm (plain fp32 output)
// ---------------------------------------------------------------------------
__global__ __launch_bounds__(256) void rmsnorm_kernel(
    const float* __restrict__ x, const float* __restrict__ scale,
    float* __restrict__ out)
{
    const int row = blockIdx.x;
    const float* xr = x + (size_t)row * HID;
    float s = 0.f;
    for (int i = threadIdx.x; i < HID; i += 256) { float v = xr[i]; s += v * v; }
    __shared__ float red[256];
    red[threadIdx.x] = s;
    __syncthreads();
    for (int off = 128; off > 0; off >>= 1) {
        if (threadIdx.x < off) red[threadIdx.x] += red[threadIdx.x + off];
        __syncthreads();
    }
    const float inv = rsqrtf(red[0] / (float)HID + EPSF);
    float* orow = out + (size_t)row * HID;
    for (int i = threadIdx.x; i < HID; i += 256)
        orow[i] = xr[i] * inv * scale[i];
}

// ---------------------------------------------------------------------------
// QKV reduce (6 slices) + bias + RoPE -> qkv
// ---------------------------------------------------------------------------
__global__ __launch_bounds__(256) void reduce_qkv_rope_kernel(
    const float* __restrict__ ws, const float* __restrict__ bias,
    const float* __restrict__ tab, float* __restrict__ qkv)
{
    const int t = blockIdx.x;
    const int tid = threadIdx.x;
    const size_t SL = (size_t)T_TOK * QKV_DIM;
    const float* base = ws + (size_t)t * QKV_DIM;
    float* outr = qkv + (size_t)t * QKV_DIM;
    const float* tr = tab + t * 64;

    for (int p = tid; p < 72 * 32; p += 256) {
        const int head = p >> 5, d = p & 31;
        const int c1 = head * 64 + d, c2 = c1 + 32;
        float s1 = bias[c1], s2 = bias[c2];
        #pragma unroll
        for (int z = 0; z < 6; z++) {
            s1 += base[z * SL + c1];
            s2 += base[z * SL + c2];
        }
        const float cc = tr[d], ss = tr[32 + d];
        outr[c1] = s1 * cc - s2 * ss;
        outr[c2] = s2 * cc + s1 * ss;
    }
    for (int c = 4608 + tid; c < QKV_DIM; c += 256) {
        float s = bias[c];
        #pragma unroll
        for (int z = 0; z < 6; z++) s += base[z * SL + c];
        outr[c] = s;
    }
}

// ---------------------------------------------------------------------------
// out reduce (3) + bias + residual -> h, then rmsnorm -> fp32 g_t
// ---------------------------------------------------------------------------
__global__ __launch_bounds__(256) void reduce_out_rms_kernel(
    const float* __restrict__ ws, const float* __restrict__ bias,
    const float* __restrict__ res, const float* __restrict__ scale,
    float* __restrict__ h, float* __restrict__ tn)
{
    __shared__ float row[HID];
    __shared__ float red[256];
    const int t = blockIdx.x;
    const int tid = threadIdx.x;
    const size_t SL = (size_t)T_TOK * NPAD_OUT;
    const float* base = ws + (size_t)t * NPAD_OUT;
    const float* xr = res + (size_t)t * HID;
    float* hr = h + (size_t)t * HID;

    float sq = 0.f;
    for (int c = tid * 4; c < HID; c += 1024) {
        const float4 a = *(const float4*)(base + c);
        const float4 b = *(const float4*)(base + SL + c);
        const float4 d = *(const float4*)(base + 2 * SL + c);
        const float4 bb = *(const float4*)(bias + c);
        const float4 rv = *(const float4*)(xr + c);
        float4 v;
        v.x = a.x + b.x + d.x + bb.x + rv.x;
        v.y = a.y + b.y + d.y + bb.y + rv.y;
        v.z = a.z + b.z + d.z + bb.z + rv.z;
        v.w = a.w + b.w + d.w + bb.w + rv.w;
        *(float4*)(row + c) = v;
        *(float4*)(hr + c) = v;
        sq += v.x * v.x + v.y * v.y + v.z * v.z + v.w * v.w;
    }
    red[tid] = sq;
    __syncthreads();
    for (int off = 128; off > 0; off >>= 1) {
        if (tid < off) red[tid] += red[tid + off];
        __syncthreads();
    }
    const float inv = rsqrtf(red[0] / (float)HID + EPSF);
    float* tr = tn + (size_t)t * HID;
    for (int c = tid * 4; c < HID; c += 1024) {
        float4 v = *(const float4*)(row + c);
        float4 sc = *(const float4*)(scale + c);
        v.x *= inv * sc.x; v.y *= inv * sc.y;
        v.z *= inv * sc.z; v.w *= inv * sc.w;
        *(float4*)(tr + c) = v;
    }
}

// ---------------------------------------------------------------------------
// up reduce (4 slices) + bias + clamped SwiGLU -> fp32 g_act
// ---------------------------------------------------------------------------
__global__ __launch_bounds__(256) void reduce_up_act_kernel(
    const float* __restrict__ ws, const float* __restrict__ bias,
    float* __restrict__ act)
{
    const int t = blockIdx.y;
    const int j = blockIdx.x * 256 + threadIdx.x;
    if (j >= INTER / 2) return;
    const int c = j * 4;
    const size_t SL = (size_t)T_TOK * NPAD_UP;
    const float* base = ws + (size_t)t * NPAD_UP + c;
    const float4 a = *(const float4*)base;
    const float4 b = *(const float4*)(base + SL);
    const float4 d = *(const float4*)(base + 2 * SL);
    const float4 e = *(const float4*)(base + 3 * SL);
    const float4 bb = *(const float4*)(bias + c);
    float u0 = a.x + b.x + d.x + e.x + bb.x;
    float u1 = a.y + b.y + d.y + e.y + bb.y;
    float u2 = a.z + b.z + d.z + e.z + bb.z;
    float u3 = a.w + b.w + d.w + e.w + bb.w;

    float g0 = fminf(u0, 7.f), l0 = fminf(fmaxf(u1, -7.f), 7.f);
    float g1 = fminf(u2, 7.f), l1 = fminf(fmaxf(u3, -7.f), 7.f);
    const float v0 = g0 / (1.f + fast_exp(-1.702f * g0)) * (l0 + 1.f);
    const float v1 = g1 / (1.f + fast_exp(-1.702f * g1)) * (l1 + 1.f);

    *(float2*)(act + (size_t)t * INTER + 2 * j) = make_float2(v0, v1);
}

// ---------------------------------------------------------------------------
// dn reduce (3) + bias + residual -> out (final)
// ---------------------------------------------------------------------------
__global__ __launch_bounds__(256) void reduce_dn_kernel(
    const float* __restrict__ ws, const float* __restrict__ bias,
    const float* __restrict__ res, float* __restrict__ C)
{
    const int idx = blockIdx.x * 256 + threadIdx.x;
    const int q = HID >> 2;
    if (idx >= T_TOK * q) return;
    const int m = idx / q;
    const int col = (idx - m * q) * 4;
    const size_t SL = (size_t)T_TOK * NPAD_DN;
    const float* p = ws + (size_t)m * NPAD_DN + col;
    const float4 a = *(const float4*)p;
    const float4 b = *(const float4*)(p + SL);
    const float4 c = *(const float4*)(p + 2 * SL);
    const float4 bb = *(const float4*)(bias + col);
    const float4 r = *(const float4*)(res + (size_t)m * HID + col);
    float4 v;
    v.x = a.x + b.x + c.x + bb.x + r.x;
    v.y = a.y + b.y + c.y + bb.y + r.y;
    v.z = a.z + b.z + c.z + bb.z + r.z;
    v.w = a.w + b.w + c.w + bb.w + r.w;
    *(float4*)(C + (size_t)m * HID + col) = v;
}

// ---------------------------------------------------------------------------
// Causal GQA flash attention, QT=64, cp.async K/V pipeline, warp-local softmax.
// Heavy q-tiles scheduled first (reversed blockIdx.x).
// ---------------------------------------------------------------------------
#define ATQ 68
#define ATV 72
#define ATTN_SMEM ((2*64*ATQ + 2*64*ATQ + 2*64*ATV + 3*64) * (int)sizeof(float))

__global__ __launch_bounds__(256) void attn_mma_kernel(
    const float* __restrict__ qkv, float* __restrict__ og)
{
    extern __shared__ float sm[];
    float* Qs   = sm;
    float* Ss   = Qs + 64 * ATQ;
    float* Ks   = Ss + 64 * ATQ;
    float* Vs   = Ks + 2 * 64 * ATQ;
    float* mrow = Vs + 2 * 64 * ATV;
    float* lrow = mrow + 64;
    float* arow = lrow + 64;

    const int qt = gridDim.x - 1 - blockIdx.x;   // heavy tiles first
    const int h = blockIdx.y, kh = h >> 3;
    const int tid = threadIdx.x, wid = tid >> 5, lane = tid & 31;
    const int wm = wid >> 2, wn = wid & 3;
    const int g = lane >> 2, qd = lane & 3;
    const int srow = tid >> 2;
    const int part = tid & 3;
    const uint32_t sbase = smem_u32(sm);
    const uint32_t kB = sbase + (2 * 64 * ATQ) * 4;
    const uint32_t vB = sbase + (2 * 64 * ATQ + 2 * 64 * ATQ) * 4;

    for (int i = tid; i < 64 * 64; i += 256) {
        int r = i >> 6, d = i & 63;
        Qs[r * ATQ + d] = tf32r(qkv[(size_t)(qt * 64 + r) * QKV_DIM + h * HD + d]);
    }
    if (tid < 64) { mrow[tid] = -1e30f; lrow[tid] = 0.f; }
    float o[2][2][4];
    #pragma unroll
    for (int i = 0; i < 2; i++)
        #pragma unroll
        for (int j = 0; j < 2; j++)
            #pragma unroll
            for (int q = 0; q < 4; q++) o[i][j][q] = 0.f;

    {
        #pragma unroll
        for (int i = 0; i < 4; i++) {
            int q = tid + 256 * i;
            int r = q >> 4, c = q & 15;
            size_t base = (size_t)r * QKV_DIM;
            cp16(kB + r * (ATQ * 4) + c * 16, qkv + base + NH * HD + kh * HD + c * 4);
            cp16(vB + r * (ATV * 4) + c * 16, qkv + base + (NH + KVH) * HD + kh * HD + c * 4);
        }
        cp_commit();
    }
    __syncthreads();

    for (int kt = 0; kt <= qt; kt++) {
        const int b = kt & 1;
        if (kt + 1 <= qt) {
            const int nb = (kt + 1) & 1;
            #pragma unroll
            for (int i = 0; i < 4; i++) {
                int q = tid + 256 * i;
                int r = q >> 4, c = q & 15;
                size_t base = (size_t)((kt + 1) * 64 + r) * QKV_DIM;
                cp16(kB + (nb * 64 + r) * (ATQ * 4) + c * 16,
                     qkv + base + NH * HD + kh * HD + c * 4);
                cp16(vB + (nb * 64 + r) * (ATV * 4) + c * 16,
                     qkv + base + (NH + KVH) * HD + kh * HD + c * 4);
            }
            cp_commit();
            cp_wait1();
        } else {
            cp_wait0();
        }
        __syncthreads();

        const float* Kb = Ks + b * 64 * ATQ;
        const float* Vb = Vs + b * 64 * ATV;

        float s[2][2][4];
        #pragma unroll
        for (int i = 0; i < 2; i++)
            #pragma unroll
            for (int j = 0; j < 2; j++)
                #pragma unroll
                for (int q = 0; q < 4; q++) s[i][j][q] = 0.f;
        #pragma unroll
        for (int k8 = 0; k8 < 8; k8++) {
            const int k0 = k8 * 8;
            uint32_t a[2][4], bfr[2][2];
            #pragma unroll
            for (int mf = 0; mf < 2; mf++) {
                const int rb = wm * 32 + mf * 16;
                a[mf][0] = __float_as_uint(Qs[(rb + g) * ATQ + k0 + qd]);
                a[mf][1] = __float_as_uint(Qs[(rb + g + 8) * ATQ + k0 + qd]);
                a[mf][2] = __float_as_uint(Qs[(rb + g) * ATQ + k0 + 4 + qd]);
                a[mf][3] = __float_as_uint(Qs[(rb + g + 8) * ATQ + k0 + 4 + qd]);
            }
            #pragma unroll
            for (int nf = 0; nf < 2; nf++) {
                const int nb2 = wn * 16 + nf * 8;
                bfr[nf][0] = tf32u(Kb[(nb2 + g) * ATQ + k0 + qd]);
                bfr[nf][1] = tf32u(Kb[(nb2 + g) * ATQ + k0 + 4 + qd]);
            }
            #pragma unroll
            for (int mf = 0; mf < 2; mf++)
                #pragma unroll
                for (int nf = 0; nf < 2; nf++)
                    mma_tf32(s[mf][nf], a[mf], bfr[nf]);
        }
        #pragma unroll
        for (int mf = 0; mf < 2; mf++)
            #pragma unroll
            for (int nf = 0; nf < 2; nf++) {
                const int r0 = wm * 32 + mf * 16 + g;
                const int c0 = wn * 16 + nf * 8 + 2 * qd;
                *(float2*)&Ss[r0 * ATQ + c0] =
                    make_float2(s[mf][nf][0] * SM_SCALE, s[mf][nf][1] * SM_SCALE);
                *(float2*)&Ss[(r0 + 8) * ATQ + c0] =
                    make_float2(s[mf][nf][2] * SM_SCALE, s[mf][nf][3] * SM_SCALE);
            }
        __syncthreads();

        {
            const int cmax = (kt == qt) ? (srow + 1) : 64;
            const int c0 = part * 16;
            float mx = -1e30f;
            #pragma unroll
            for (int c = c0; c < c0 + 16; c++)
                if (c < cmax) mx = fmaxf(mx, Ss[srow * ATQ + c]);
            mx = fmaxf(mx, __shfl_xor_sync(0xFFFFFFFFu, mx, 1));
            mx = fmaxf(mx, __shfl_xor_sync(0xFFFFFFFFu, mx, 2));
            const float mold = mrow[srow];
            const float mfin = fmaxf(mold, mx);
            float sum = 0.f;
            #pragma unroll
            for (int c = c0; c < c0 + 16; c++) {
                float p = (c < cmax) ? fast_exp(Ss[srow * ATQ + c] - mfin) : 0.f;
                Ss[srow * ATQ + c] = tf32r(p);
                sum += p;
            }
            sum += __shfl_xor_sync(0xFFFFFFFFu, sum, 1);
            sum += __shfl_xor_sync(0xFFFFFFFFu, sum, 2);
            if (part == 0) {
                const float alpha = fast_exp(mold - mfin);
                mrow[srow] = mfin;
                lrow[srow] = lrow[srow] * alpha + sum;
                arow[srow] = alpha;
            }
            __syncthreads();
        }

        #pragma unroll
        for (int mf = 0; mf < 2; mf++) {
            const int r0 = wm * 32 + mf * 16 + g;
            const float al0 = arow[r0], al1 = arow[r0 + 8];
            #pragma unroll
            for (int nf = 0; nf < 2; nf++) {
                o[mf][nf][0] *= al0; o[mf][nf][1] *= al0;
                o[mf][nf][2] *= al1; o[mf][nf][3] *= al1;
            }
        }
        #pragma unroll
        for (int k8 = 0; k8 < 8; k8++) {
            const int k0 = k8 * 8;
            uint32_t a[2][4], bfr[2][2];
            #pragma unroll
            for (int mf = 0; mf < 2; mf++) {
                const int rb = wm * 32 + mf * 16;
                a[mf][0] = __float_as_uint(Ss[(rb + g) * ATQ + k0 + qd]);
                a[mf][1] = __float_as_uint(Ss[(rb + g + 8) * ATQ + k0 + qd]);
                a[mf][2] = __float_as_uint(Ss[(rb + g) * ATQ + k0 + 4 + qd]);
                a[mf][3] = __float_as_uint(Ss[(rb + g + 8) * ATQ + k0 + 4 + qd]);
            }
            #pragma unroll
            for (int nf = 0; nf < 2; nf++) {
                const int nb2 = wn * 16 + nf * 8;
                bfr[nf][0] = tf32u(Vb[(k0 + qd) * ATV + nb2 + g]);
                bfr[nf][1] = tf32u(Vb[(k0 + 4 + qd) * ATV + nb2 + g]);
            }
            #pragma unroll
            for (int mf = 0; mf < 2; mf++)
                #pragma unroll
                for (int nf = 0; nf < 2; nf++)
                    mma_tf32(o[mf][nf], a[mf], bfr[nf]);
        }
        __syncthreads();
    }

    #pragma unroll
    for (int mf = 0; mf < 2; mf++) {
        const int r0 = wm * 32 + mf * 16 + g;
        const float li0 = 1.f / lrow[r0];
        const float li1 = 1.f / lrow[r0 + 8];
        #pragma unroll
        for (int nf = 0; nf < 2; nf++) {
            const int col = h * HD + wn * 16 + nf * 8 + 2 * qd;
            *(float2*)(og + (size_t)(qt * 64 + r0) * O_DIM + col) =
                make_float2(o[mf][nf][0] * li0, o[mf][nf][1] * li0);
            *(float2*)(og + (size_t)(qt * 64 + r0 + 8) * O_DIM + col) =
                make_float2(o[mf][nf][2] * li1, o[mf][nf][3] * li1);
        }
    }
}

// ---------------------------------------------------------------------------
// Launch
// ---------------------------------------------------------------------------
static inline int cdiv_i(long long a, int b) { return (int)((a + b - 1) / b); }

extern "C" void kernel_launch(void* const* d_in, const int* in_sizes, int n_in,
                              void* d_out, int out_size)
{
    const float* x        = (const float*)d_in[0];
    const float* an_scale = (const float*)d_in[1];
    const float* wqkv     = (const float*)d_in[2];
    const float* bqkv     = (const float*)d_in[3];
    const float* wout     = (const float*)d_in[4];
    const float* bout     = (const float*)d_in[5];
    const float* mn_scale = (const float*)d_in[6];
    const float* w1       = (const float*)d_in[7];
    const float* b1       = (const float*)d_in[8];
    const float* w2       = (const float*)d_in[9];
    const float* b2       = (const float*)d_in[10];
    float* out = (float*)d_out;

    static float *qkv_p = nullptr, *h_p, *t_p, *o_p, *act_p, *ws_p, *rt_p;
    if (!qkv_p) {
        cudaGetSymbolAddress((void**)&qkv_p,  g_qkv);
        cudaGetSymbolAddress((void**)&h_p,    g_h);
        cudaGetSymbolAddress((void**)&t_p,    g_t);
        cudaGetSymbolAddress((void**)&o_p,    g_o);
        cudaGetSymbolAddress((void**)&act_p,  g_act);
        cudaGetSymbolAddress((void**)&ws_p,   g_ws);
        cudaGetSymbolAddress((void**)&rt_p,   g_rope);
    }
    cudaFuncSetAttribute(attn_mma_kernel,
                         cudaFuncAttributeMaxDynamicSharedMemorySize, ATTN_SMEM);
    cudaFuncSetAttribute(tf32_gemm_sk,
                         cudaFuncAttributeMaxDynamicSharedMemorySize, GSMEM_TOTAL);

    rope_table_kernel<<<T_TOK, 32>>>(rt_p);

    // 1) attn rmsnorm -> fp32 t
    rmsnorm_kernel<<<T_TOK, 256>>>(x, an_scale, t_p);

    // 2) QKV GEMM (tf32, S=6) + fused reduce+rope
    {
        dim3 grid(T_TOK / 128, QKV_DIM / 256, 6);
        tf32_gemm_sk<<<grid, 256, GSMEM_TOTAL>>>(t_p, wqkv, ws_p,
                                                 HID, QKV_DIM, QKV_DIM, 6);
        reduce_qkv_rope_kernel<<<T_TOK, 256>>>(ws_p, bqkv, rt_p, qkv_p);
    }

    // 3) attention -> fp32 o (heavy tiles first)
    {
        dim3 grid(T_TOK / 64, NH);
        attn_mma_kernel<<<grid, 256, ATTN_SMEM>>>(qkv_p, o_p);
    }

    // 4) out GEMM (tf32, S=3) + fused reduce+residual+rmsnorm
    {
        dim3 grid(T_TOK / 128, NPAD_OUT / 256, 3);
        tf32_gemm_sk<<<grid, 256, GSMEM_TOTAL>>>(o_p, wout, ws_p,
                                                 O_DIM, NPAD_OUT, HID, 3);
        reduce_out_rms_kernel<<<T_TOK, 256>>>(ws_p, bout, x, mn_scale, h_p, t_p);
    }

    // 5) MLP up GEMM (tf32, S=4) + fused reduce+act
    {
        dim3 grid(T_TOK / 128, NPAD_UP / 256, 4);
        tf32_gemm_sk<<<grid, 256, GSMEM_TOTAL>>>(t_p, w1, ws_p,
                                                 HID, NPAD_UP, U_DIM, 4);
        dim3 rg(cdiv_i(INTER / 2, 256), T_TOK);
        reduce_up_act_kernel<<<rg, 256>>>(ws_p, b1, act_p);
    }

    // 6) MLP down GEMM (tf32, S=3) + fused reduce+residual -> out
    {
        dim3 grid(T_TOK / 128, NPAD_DN / 256, 3);
        tf32_gemm_sk<<<grid, 256, GSMEM_TOTAL>>>(act_p, w2, ws_p,
                                                 INTER, NPAD_DN, HID, 3);
        reduce_dn_kernel<<<cdiv_i((long long)T_TOK * HID / 4, 256), 256>>>(
            ws_p, b2, h_p, out);
    }
}